// round 1
// baseline (speedup 1.0000x reference)
#include <cuda_runtime.h>
#include <math_constants.h>

// Problem constants
#define BB 8
#define TT 2048
#define EE 1024

// Scratch buffers (device globals: no allocation allowed in kernel_launch)
__device__ float g_Q[(size_t)BB * TT * EE];   // 64 MB
__device__ float g_K[(size_t)BB * TT * EE];   // 64 MB
__device__ float g_V[(size_t)BB * TT * EE];   // 64 MB
__device__ float g_S[(size_t)BB * TT * TT];   // 128 MB

// ---------------------------------------------------------------------------
// SGEMM "NT": C[M,N] = alpha * A[M,K] * B[N,K]^T   (both operands K-major)
// 128x128x8 tile, 256 threads, 8x8 per-thread accumulators.
// blockIdx.z batches with element strides sA/sB/sC.
// Requires M%128==0, N%128==0, K%8==0 (true for all our shapes).
// ---------------------------------------------------------------------------
__global__ __launch_bounds__(256)
void sgemm_nt_kernel(const float* __restrict__ A, const float* __restrict__ B,
                     float* __restrict__ C, int M, int N, int K, float alpha,
                     size_t sA, size_t sB, size_t sC)
{
    const int tid = threadIdx.x;
    const float* Ab = A + (size_t)blockIdx.z * sA + (size_t)blockIdx.y * 128 * K;
    const float* Bb = B + (size_t)blockIdx.z * sB + (size_t)blockIdx.x * 128 * K;
    float*       Cb = C + (size_t)blockIdx.z * sC + (size_t)blockIdx.y * 128 * N
                        + (size_t)blockIdx.x * 128;

    __shared__ float As[8][128];
    __shared__ float Bs[8][128];

    const int lr = tid >> 1;          // 0..127 : tile row (m for A, n for B)
    const int lc = (tid & 1) * 4;     // 0 or 4 : k offset within BK

    const int ty = tid >> 4;          // 0..15
    const int tx = tid & 15;          // 0..15

    float acc[8][8];
#pragma unroll
    for (int i = 0; i < 8; i++)
#pragma unroll
        for (int j = 0; j < 8; j++) acc[i][j] = 0.0f;

    for (int kt = 0; kt < K; kt += 8) {
        float4 av = *(const float4*)(Ab + (size_t)lr * K + kt + lc);
        float4 bv = *(const float4*)(Bb + (size_t)lr * K + kt + lc);
        As[lc + 0][lr] = av.x; As[lc + 1][lr] = av.y;
        As[lc + 2][lr] = av.z; As[lc + 3][lr] = av.w;
        Bs[lc + 0][lr] = bv.x; Bs[lc + 1][lr] = bv.y;
        Bs[lc + 2][lr] = bv.z; Bs[lc + 3][lr] = bv.w;
        __syncthreads();
#pragma unroll
        for (int k = 0; k < 8; k++) {
            float4 a0 = *(const float4*)&As[k][ty * 8];
            float4 a1 = *(const float4*)&As[k][ty * 8 + 4];
            float4 b0 = *(const float4*)&Bs[k][tx * 8];
            float4 b1 = *(const float4*)&Bs[k][tx * 8 + 4];
            float ra[8] = {a0.x, a0.y, a0.z, a0.w, a1.x, a1.y, a1.z, a1.w};
            float rb[8] = {b0.x, b0.y, b0.z, b0.w, b1.x, b1.y, b1.z, b1.w};
#pragma unroll
            for (int i = 0; i < 8; i++)
#pragma unroll
                for (int j = 0; j < 8; j++)
                    acc[i][j] += ra[i] * rb[j];
        }
        __syncthreads();
    }

#pragma unroll
    for (int i = 0; i < 8; i++) {
        float* crow = Cb + (size_t)(ty * 8 + i) * N + tx * 8;
        float4 o0 = make_float4(alpha * acc[i][0], alpha * acc[i][1],
                                alpha * acc[i][2], alpha * acc[i][3]);
        float4 o1 = make_float4(alpha * acc[i][4], alpha * acc[i][5],
                                alpha * acc[i][6], alpha * acc[i][7]);
        *(float4*)crow       = o0;
        *(float4*)(crow + 4) = o1;
    }
}

// ---------------------------------------------------------------------------
// SGEMM "NN": C[M,N] = A[M,K] * B[K,N]   (A row-major, B row-major)
// Same tiling as above; only the B-tile load path differs.
// ---------------------------------------------------------------------------
__global__ __launch_bounds__(256)
void sgemm_nn_kernel(const float* __restrict__ A, const float* __restrict__ B,
                     float* __restrict__ C, int M, int N, int K,
                     size_t sA, size_t sB, size_t sC)
{
    const int tid = threadIdx.x;
    const float* Ab = A + (size_t)blockIdx.z * sA + (size_t)blockIdx.y * 128 * K;
    const float* Bb = B + (size_t)blockIdx.z * sB + (size_t)blockIdx.x * 128;
    float*       Cb = C + (size_t)blockIdx.z * sC + (size_t)blockIdx.y * 128 * N
                        + (size_t)blockIdx.x * 128;

    __shared__ float As[8][128];
    __shared__ float Bs[8][128];

    const int lr = tid >> 1;           // 0..127 : A tile row
    const int lc = (tid & 1) * 4;      // 0 or 4 : A k offset

    const int br = tid >> 5;           // 0..7   : B tile k row
    const int bc = (tid & 31) * 4;     // 0..124 : B tile col

    const int ty = tid >> 4;
    const int tx = tid & 15;

    float acc[8][8];
#pragma unroll
    for (int i = 0; i < 8; i++)
#pragma unroll
        for (int j = 0; j < 8; j++) acc[i][j] = 0.0f;

    for (int kt = 0; kt < K; kt += 8) {
        float4 av = *(const float4*)(Ab + (size_t)lr * K + kt + lc);
        float4 bv = *(const float4*)(Bb + (size_t)(kt + br) * N + bc);
        As[lc + 0][lr] = av.x; As[lc + 1][lr] = av.y;
        As[lc + 2][lr] = av.z; As[lc + 3][lr] = av.w;
        *(float4*)&Bs[br][bc] = bv;
        __syncthreads();
#pragma unroll
        for (int k = 0; k < 8; k++) {
            float4 a0 = *(const float4*)&As[k][ty * 8];
            float4 a1 = *(const float4*)&As[k][ty * 8 + 4];
            float4 b0 = *(const float4*)&Bs[k][tx * 8];
            float4 b1 = *(const float4*)&Bs[k][tx * 8 + 4];
            float ra[8] = {a0.x, a0.y, a0.z, a0.w, a1.x, a1.y, a1.z, a1.w};
            float rb[8] = {b0.x, b0.y, b0.z, b0.w, b1.x, b1.y, b1.z, b1.w};
#pragma unroll
            for (int i = 0; i < 8; i++)
#pragma unroll
                for (int j = 0; j < 8; j++)
                    acc[i][j] += ra[i] * rb[j];
        }
        __syncthreads();
    }

#pragma unroll
    for (int i = 0; i < 8; i++) {
        float* crow = Cb + (size_t)(ty * 8 + i) * N + tx * 8;
        float4 o0 = make_float4(acc[i][0], acc[i][1], acc[i][2], acc[i][3]);
        float4 o1 = make_float4(acc[i][4], acc[i][5], acc[i][6], acc[i][7]);
        *(float4*)crow       = o0;
        *(float4*)(crow + 4) = o1;
    }
}

// ---------------------------------------------------------------------------
// Masked row softmax in-place on S[B*T, T]. mask is [T, T] int32 shared
// across batch; mask==0 -> -inf before softmax. One block per row.
// ---------------------------------------------------------------------------
__global__ __launch_bounds__(256)
void softmax_mask_kernel(float* __restrict__ S, const int* __restrict__ mask)
{
    const int row = blockIdx.x;          // b*T + t
    const int t   = row & (TT - 1);      // T is a power of two
    float* Srow = S + (size_t)row * TT;
    const int* mrow = mask + (size_t)t * TT;
    const int tid = threadIdx.x;

    float v[8];
    float m = -CUDART_INF_F;
#pragma unroll
    for (int i = 0; i < 8; i++) {
        int s = tid + i * 256;
        float x = (mrow[s] != 0) ? Srow[s] : -CUDART_INF_F;
        v[i] = x;
        m = fmaxf(m, x);
    }

    __shared__ float red[256];
    red[tid] = m;
    __syncthreads();
    for (int off = 128; off > 0; off >>= 1) {
        if (tid < off) red[tid] = fmaxf(red[tid], red[tid + off]);
        __syncthreads();
    }
    m = red[0];
    __syncthreads();

    float sum = 0.0f;
#pragma unroll
    for (int i = 0; i < 8; i++) {
        float e = __expf(v[i] - m);   // exp(-inf) = 0 for masked entries
        v[i] = e;
        sum += e;
    }
    red[tid] = sum;
    __syncthreads();
    for (int off = 128; off > 0; off >>= 1) {
        if (tid < off) red[tid] += red[tid + off];
        __syncthreads();
    }
    const float inv = 1.0f / red[0];

#pragma unroll
    for (int i = 0; i < 8; i++)
        Srow[tid + i * 256] = v[i] * inv;
}

// ---------------------------------------------------------------------------
// kernel_launch: 3 projection GEMMs -> batched QK^T -> masked softmax -> PV
// ---------------------------------------------------------------------------
extern "C" void kernel_launch(void* const* d_in, const int* in_sizes, int n_in,
                              void* d_out, int out_size)
{
    const float* q    = (const float*)d_in[0];
    const float* k    = (const float*)d_in[1];
    const float* v    = (const float*)d_in[2];
    const int*   mask = (const int*)  d_in[3];
    const float* Wq   = (const float*)d_in[4];
    const float* Wk   = (const float*)d_in[5];
    const float* Wv   = (const float*)d_in[6];
    float* out = (float*)d_out;

    float *pQ, *pK, *pV, *pS;
    cudaGetSymbolAddress((void**)&pQ, g_Q);
    cudaGetSymbolAddress((void**)&pK, g_K);
    cudaGetSymbolAddress((void**)&pV, g_V);
    cudaGetSymbolAddress((void**)&pS, g_S);

    const int M  = BB * TT;   // 16384
    const size_t strideQKV = (size_t)TT * EE;
    const size_t strideS   = (size_t)TT * TT;

    // 1-3) Projections: P = X @ W^T   (M=16384, N=1024, K=1024), NT form
    dim3 gProj(EE / 128, M / 128, 1);
    sgemm_nt_kernel<<<gProj, 256>>>(q, Wq, pQ, M, EE, EE, 1.0f, 0, 0, 0);
    sgemm_nt_kernel<<<gProj, 256>>>(k, Wk, pK, M, EE, EE, 1.0f, 0, 0, 0);
    sgemm_nt_kernel<<<gProj, 256>>>(v, Wv, pV, M, EE, EE, 1.0f, 0, 0, 0);

    // 4) Scores: S_b = (Q_b @ K_b^T) / 32   (batched NT, M=N=2048, K=1024)
    dim3 gScore(TT / 128, TT / 128, BB);
    sgemm_nt_kernel<<<gScore, 256>>>(pQ, pK, pS, TT, TT, EE, 1.0f / 32.0f,
                                     strideQKV, strideQKV, strideS);

    // 5) Masked softmax over last dim, in place
    softmax_mask_kernel<<<BB * TT, 256>>>(pS, mask);

    // 6) Output: O_b = P_b @ V_b   (batched NN, M=2048, N=1024, K=2048)
    dim3 gOut(EE / 128, TT / 128, BB);
    sgemm_nn_kernel<<<gOut, 256>>>(pS, pV, out, TT, EE, TT,
                                   strideS, strideQKV, strideQKV);
}

// round 3
// speedup vs baseline: 2.3693x; 2.3693x over previous
#include <cuda_runtime.h>
#include <cuda_fp16.h>
#include <math_constants.h>
#include <cstdint>

// Problem constants
#define BB 8
#define TT 2048
#define EE 1024
#define NQKV ((size_t)BB * TT * EE)   // 16,777,216
#define NS   ((size_t)BB * TT * TT)   // 33,554,432

// ---------------------------------------------------------------------------
// Scratch (device globals; allocation forbidden in kernel_launch)
// ---------------------------------------------------------------------------
__device__ __half g_qh[NQKV], g_ql[NQKV];
__device__ __half g_kh[NQKV], g_kl[NQKV];
__device__ __half g_vh[NQKV], g_vl[NQKV];
__device__ __half g_Wqh[EE * EE], g_Wql[EE * EE];
__device__ __half g_Wkh[EE * EE], g_Wkl[EE * EE];
__device__ __half g_Wvh[EE * EE], g_Wvl[EE * EE];
__device__ __half g_Qh[NQKV], g_Ql[NQKV];
__device__ __half g_Kh[NQKV], g_Kl[NQKV];
__device__ float  g_V[NQKV];
__device__ __half g_VTh[NQKV], g_VTl[NQKV];
__device__ float  g_S[NS];
__device__ __half g_Ph[NS], g_Pl[NS];

// ---------------------------------------------------------------------------
// Helpers
// ---------------------------------------------------------------------------
__device__ __forceinline__ uint32_t smem_u32(const void* p) {
    uint32_t a;
    asm("{ .reg .u64 t; cvta.to.shared.u64 t, %1; cvt.u32.u64 %0, t; }"
        : "=r"(a) : "l"(p));
    return a;
}

__device__ __forceinline__ void cp16(uint32_t dst_smem, const void* src_gmem) {
    asm volatile("cp.async.cg.shared.global [%0], [%1], 16;"
                 :: "r"(dst_smem), "l"(__cvta_generic_to_global(src_gmem)));
}
#define CP_COMMIT() asm volatile("cp.async.commit_group;" ::: "memory")
#define CP_WAIT0()  asm volatile("cp.async.wait_group 0;"  ::: "memory")

__device__ __forceinline__ uint32_t lds32(uint32_t addr) {
    uint32_t v;
    asm volatile("ld.shared.b32 %0, [%1];" : "=r"(v) : "r"(addr));
    return v;
}

// m16n8k16 fp16 -> fp32 accumulate
__device__ __forceinline__ void mma16816(float* c,
                                         uint32_t a0, uint32_t a1, uint32_t a2, uint32_t a3,
                                         uint32_t b0, uint32_t b1) {
    asm volatile(
        "mma.sync.aligned.m16n8k16.row.col.f32.f16.f16.f32 "
        "{%0,%1,%2,%3}, {%4,%5,%6,%7}, {%8,%9}, {%0,%1,%2,%3};"
        : "+f"(c[0]), "+f"(c[1]), "+f"(c[2]), "+f"(c[3])
        : "r"(a0), "r"(a1), "r"(a2), "r"(a3), "r"(b0), "r"(b1));
}

__device__ __forceinline__ void split2(float x, __half& h, __half& l) {
    h = __float2half_rn(x);
    l = __float2half_rn(x - __half2float(h));
}

// ---------------------------------------------------------------------------
// Elementwise split: fp32 -> (hi, lo) fp16 pair. n % 4 == 0.
// ---------------------------------------------------------------------------
__global__ __launch_bounds__(256)
void split_kernel(const float* __restrict__ x, __half* __restrict__ hi,
                  __half* __restrict__ lo, size_t n)
{
    size_t i = ((size_t)blockIdx.x * blockDim.x + threadIdx.x) * 4;
    if (i >= n) return;
    float4 v = *(const float4*)(x + i);
    __half h0, h1, h2, h3, l0, l1, l2, l3;
    split2(v.x, h0, l0); split2(v.y, h1, l1);
    split2(v.z, h2, l2); split2(v.w, h3, l3);
    ((__half2*)hi)[i / 2]     = __halves2half2(h0, h1);
    ((__half2*)hi)[i / 2 + 1] = __halves2half2(h2, h3);
    ((__half2*)lo)[i / 2]     = __halves2half2(l0, l1);
    ((__half2*)lo)[i / 2 + 1] = __halves2half2(l2, l3);
}

// ---------------------------------------------------------------------------
// Split-FP16 NT GEMM on tensor cores (mma.sync m16n8k16):
//   C[M,N] = alpha * (Ah+Al)[M,K] * (Bh+Bl)[N,K]^T   (3-pass, AloBlo dropped)
// CTA: 128x128x32, 256 threads = 8 warps (2 x 4), warp tile 64x32.
// SMEM: 2 stages x 4 tiles (Ah, Al, Bh, Bl), each 128 rows x 80B (64B data).
// OUT_MODE 0: write fp32 C.  OUT_MODE 1: write split fp16 (Ch, Cl).
// Requires M%128==0, N%128==0, K%32==0.
// ---------------------------------------------------------------------------
#define SROW 80
#define TILE_B (128 * SROW)            // 10240
#define STAGE_B (4 * TILE_B)           // 40960
#define GEMM_SMEM (2 * STAGE_B)        // 81920

template <int OUT_MODE>
__global__ __launch_bounds__(256, 1)
void gemm_f16pair_nt(const __half* __restrict__ Ah, const __half* __restrict__ Al,
                     const __half* __restrict__ Bh, const __half* __restrict__ Bl,
                     float* __restrict__ C, __half* __restrict__ Ch,
                     __half* __restrict__ Cl,
                     int M, int N, int K, float alpha,
                     size_t sA, size_t sB, size_t sC)
{
    extern __shared__ __align__(128) char smem[];
    const uint32_t sb = smem_u32(smem);

    const int tid  = threadIdx.x;
    const int wid  = tid >> 5;
    const int lane = tid & 31;
    const int wm   = wid >> 2;          // 0..1
    const int wn   = wid & 3;           // 0..3
    const int g    = lane >> 2;         // 0..7
    const int i4   = lane & 3;          // 0..3

    const size_t z = blockIdx.z;
    const __half* pAh = Ah + z * sA;
    const __half* pAl = Al + z * sA;
    const __half* pBh = Bh + z * sB;
    const __half* pBl = Bl + z * sB;

    const int aRow0 = blockIdx.y * 128;
    const int bRow0 = blockIdx.x * 128;

    // copy indices: 2 iterations, idx = tid + t*256 -> row=idx>>2, q=idx&3
    const int cr0 = tid >> 2;            // rows 0..63
    const int cq  = (tid & 3);           // 16B quarter 0..3

    float acc[4][4][4];
#pragma unroll
    for (int a = 0; a < 4; a++)
#pragma unroll
        for (int b = 0; b < 4; b++)
#pragma unroll
            for (int c = 0; c < 4; c++) acc[a][b][c] = 0.0f;

    const int nch = K >> 5;

    auto issue = [&](int kc) {
        const int buf = kc & 1;
        const uint32_t tb = sb + buf * STAGE_B;
        const int kofs = kc << 5;
#pragma unroll
        for (int t = 0; t < 2; t++) {
            const int r = cr0 + t * 64;
            const uint32_t so = (uint32_t)(r * SROW + cq * 16);
            const size_t goA = (size_t)(aRow0 + r) * K + kofs + cq * 8;
            const size_t goB = (size_t)(bRow0 + r) * K + kofs + cq * 8;
            cp16(tb + 0 * TILE_B + so, pAh + goA);
            cp16(tb + 1 * TILE_B + so, pAl + goA);
            cp16(tb + 2 * TILE_B + so, pBh + goB);
            cp16(tb + 3 * TILE_B + so, pBl + goB);
        }
        CP_COMMIT();
    };

    issue(0);

    for (int kc = 0; kc < nch; kc++) {
        CP_WAIT0();
        __syncthreads();
        if (kc + 1 < nch) issue(kc + 1);

        const uint32_t tb = sb + (kc & 1) * STAGE_B;
#pragma unroll
        for (int h = 0; h < 2; h++) {
            // A fragments (hi and lo) for all 4 m-frags
            uint32_t ah[4][4], al[4][4];
#pragma unroll
            for (int fm = 0; fm < 4; fm++) {
                const uint32_t r0 = tb + (uint32_t)((wm * 64 + fm * 16 + g) * SROW
                                                    + h * 32 + i4 * 4);
                const uint32_t r1 = r0 + 8 * SROW;
                ah[fm][0] = lds32(r0);
                ah[fm][1] = lds32(r1);
                ah[fm][2] = lds32(r0 + 16);
                ah[fm][3] = lds32(r1 + 16);
                al[fm][0] = lds32(r0 + TILE_B);
                al[fm][1] = lds32(r1 + TILE_B);
                al[fm][2] = lds32(r0 + TILE_B + 16);
                al[fm][3] = lds32(r1 + TILE_B + 16);
            }
#pragma unroll
            for (int fn = 0; fn < 4; fn++) {
                const uint32_t nb = tb + 2 * TILE_B
                                  + (uint32_t)((wn * 32 + fn * 8 + g) * SROW
                                               + h * 32 + i4 * 4);
                const uint32_t bh0 = lds32(nb);
                const uint32_t bh1 = lds32(nb + 16);
                const uint32_t bl0 = lds32(nb + TILE_B);
                const uint32_t bl1 = lds32(nb + TILE_B + 16);
#pragma unroll
                for (int fm = 0; fm < 4; fm++) {
                    mma16816(acc[fm][fn], ah[fm][0], ah[fm][1], ah[fm][2], ah[fm][3], bh0, bh1);
                    mma16816(acc[fm][fn], ah[fm][0], ah[fm][1], ah[fm][2], ah[fm][3], bl0, bl1);
                    mma16816(acc[fm][fn], al[fm][0], al[fm][1], al[fm][2], al[fm][3], bh0, bh1);
                }
            }
        }
        __syncthreads();
    }

    // Epilogue
    const int rowB = aRow0 + wm * 64 + g;
    const int colB = bRow0 + wn * 32 + i4 * 2;
#pragma unroll
    for (int fm = 0; fm < 4; fm++) {
#pragma unroll
        for (int fn = 0; fn < 4; fn++) {
            const int row = rowB + fm * 16;
            const int col = colB + fn * 8;
            float c0 = alpha * acc[fm][fn][0];
            float c1 = alpha * acc[fm][fn][1];
            float c2 = alpha * acc[fm][fn][2];
            float c3 = alpha * acc[fm][fn][3];
            if (OUT_MODE == 0) {
                float* pc = C + z * sC;
                *(float2*)(pc + (size_t)row * N + col)       = make_float2(c0, c1);
                *(float2*)(pc + (size_t)(row + 8) * N + col) = make_float2(c2, c3);
            } else {
                __half* ph = Ch + z * sC;
                __half* pl = Cl + z * sC;
                __half h0, h1, h2, h3, l0, l1, l2, l3;
                split2(c0, h0, l0); split2(c1, h1, l1);
                split2(c2, h2, l2); split2(c3, h3, l3);
                *(__half2*)(ph + (size_t)row * N + col)       = __halves2half2(h0, h1);
                *(__half2*)(pl + (size_t)row * N + col)       = __halves2half2(l0, l1);
                *(__half2*)(ph + (size_t)(row + 8) * N + col) = __halves2half2(h2, h3);
                *(__half2*)(pl + (size_t)(row + 8) * N + col) = __halves2half2(l2, l3);
            }
        }
    }
}

// ---------------------------------------------------------------------------
// Transpose + split: V[b][s][o] fp32 -> VThi/VTlo[b][o][s] fp16
// ---------------------------------------------------------------------------
__global__ __launch_bounds__(256)
void transpose_split_kernel(const float* __restrict__ V,
                            __half* __restrict__ Th, __half* __restrict__ Tl)
{
    __shared__ float t[32][33];
    const int b  = blockIdx.z;
    const int s0 = blockIdx.x << 5;
    const int o0 = blockIdx.y << 5;
    const float* Vb = V + (size_t)b * TT * EE;
    __half* Thb = Th + (size_t)b * EE * TT;
    __half* Tlb = Tl + (size_t)b * EE * TT;
    const int tx = threadIdx.x & 31;
    const int ty = threadIdx.x >> 5;
#pragma unroll
    for (int i = 0; i < 4; i++)
        t[ty + 8 * i][tx] = Vb[(size_t)(s0 + ty + 8 * i) * EE + o0 + tx];
    __syncthreads();
#pragma unroll
    for (int i = 0; i < 4; i++) {
        float x = t[tx][ty + 8 * i];
        __half h, l;
        split2(x, h, l);
        const size_t off = (size_t)(o0 + ty + 8 * i) * TT + s0 + tx;
        Thb[off] = h;
        Tlb[off] = l;
    }
}

// ---------------------------------------------------------------------------
// Masked row softmax: S[B*T, T] fp32 -> split fp16 (Ph, Pl). mask 0 -> -inf.
// ---------------------------------------------------------------------------
__global__ __launch_bounds__(256)
void softmax_split_kernel(const float* __restrict__ S, const int* __restrict__ mask,
                          __half* __restrict__ Ph, __half* __restrict__ Pl)
{
    const int row = blockIdx.x;
    const int t   = row & (TT - 1);
    const float* Srow = S + (size_t)row * TT;
    const int* mrow = mask + (size_t)t * TT;
    const int tid = threadIdx.x;

    float v[8];
    float m = -CUDART_INF_F;
#pragma unroll
    for (int i = 0; i < 8; i++) {
        int s = tid + i * 256;
        float x = (mrow[s] != 0) ? Srow[s] : -CUDART_INF_F;
        v[i] = x;
        m = fmaxf(m, x);
    }

    __shared__ float red[256];
    red[tid] = m;
    __syncthreads();
    for (int off = 128; off > 0; off >>= 1) {
        if (tid < off) red[tid] = fmaxf(red[tid], red[tid + off]);
        __syncthreads();
    }
    m = red[0];
    __syncthreads();

    float sum = 0.0f;
#pragma unroll
    for (int i = 0; i < 8; i++) {
        float e = __expf(v[i] - m);
        v[i] = e;
        sum += e;
    }
    red[tid] = sum;
    __syncthreads();
    for (int off = 128; off > 0; off >>= 1) {
        if (tid < off) red[tid] += red[tid + off];
        __syncthreads();
    }
    const float inv = 1.0f / red[0];

    __half* Phr = Ph + (size_t)row * TT;
    __half* Plr = Pl + (size_t)row * TT;
#pragma unroll
    for (int i = 0; i < 8; i++) {
        float p = v[i] * inv;
        __half h, l;
        split2(p, h, l);
        Phr[tid + i * 256] = h;
        Plr[tid + i * 256] = l;
    }
}

// ---------------------------------------------------------------------------
// kernel_launch
// ---------------------------------------------------------------------------
extern "C" void kernel_launch(void* const* d_in, const int* in_sizes, int n_in,
                              void* d_out, int out_size)
{
    const float* q    = (const float*)d_in[0];
    const float* k    = (const float*)d_in[1];
    const float* v    = (const float*)d_in[2];
    const int*   mask = (const int*)  d_in[3];
    const float* Wq   = (const float*)d_in[4];
    const float* Wk   = (const float*)d_in[5];
    const float* Wv   = (const float*)d_in[6];
    float* out = (float*)d_out;

    __half *qh, *ql, *kh, *kl, *vh, *vl;
    __half *wqh, *wql, *wkh, *wkl, *wvh, *wvl;
    __half *Qh, *Ql, *Kh, *Kl, *VTh, *VTl, *Ph, *Pl;
    float *V, *S;
    cudaGetSymbolAddress((void**)&qh,  g_qh);  cudaGetSymbolAddress((void**)&ql,  g_ql);
    cudaGetSymbolAddress((void**)&kh,  g_kh);  cudaGetSymbolAddress((void**)&kl,  g_kl);
    cudaGetSymbolAddress((void**)&vh,  g_vh);  cudaGetSymbolAddress((void**)&vl,  g_vl);
    cudaGetSymbolAddress((void**)&wqh, g_Wqh); cudaGetSymbolAddress((void**)&wql, g_Wql);
    cudaGetSymbolAddress((void**)&wkh, g_Wkh); cudaGetSymbolAddress((void**)&wkl, g_Wkl);
    cudaGetSymbolAddress((void**)&wvh, g_Wvh); cudaGetSymbolAddress((void**)&wvl, g_Wvl);
    cudaGetSymbolAddress((void**)&Qh,  g_Qh);  cudaGetSymbolAddress((void**)&Ql,  g_Ql);
    cudaGetSymbolAddress((void**)&Kh,  g_Kh);  cudaGetSymbolAddress((void**)&Kl,  g_Kl);
    cudaGetSymbolAddress((void**)&VTh, g_VTh); cudaGetSymbolAddress((void**)&VTl, g_VTl);
    cudaGetSymbolAddress((void**)&Ph,  g_Ph);  cudaGetSymbolAddress((void**)&Pl,  g_Pl);
    cudaGetSymbolAddress((void**)&V,   g_V);
    cudaGetSymbolAddress((void**)&S,   g_S);

    cudaFuncSetAttribute(gemm_f16pair_nt<0>,
                         cudaFuncAttributeMaxDynamicSharedMemorySize, GEMM_SMEM);
    cudaFuncSetAttribute(gemm_f16pair_nt<1>,
                         cudaFuncAttributeMaxDynamicSharedMemorySize, GEMM_SMEM);

    const int M = BB * TT;                   // 16384
    const size_t strQKV = (size_t)TT * EE;
    const size_t strS   = (size_t)TT * TT;
    const size_t strVT  = (size_t)EE * TT;

    // 0) Split fp32 inputs into fp16 (hi, lo) pairs
    {
        const int nb_big = (int)(NQKV / (256 * 4));
        const int nb_w   = (EE * EE) / (256 * 4);
        split_kernel<<<nb_big, 256>>>(q,  qh,  ql,  NQKV);
        split_kernel<<<nb_big, 256>>>(k,  kh,  kl,  NQKV);
        split_kernel<<<nb_big, 256>>>(v,  vh,  vl,  NQKV);
        split_kernel<<<nb_w,   256>>>(Wq, wqh, wql, (size_t)EE * EE);
        split_kernel<<<nb_w,   256>>>(Wk, wkh, wkl, (size_t)EE * EE);
        split_kernel<<<nb_w,   256>>>(Wv, wvh, wvl, (size_t)EE * EE);
    }

    // 1-3) Projections (M=16384, N=1024, K=1024)
    dim3 gProj(EE / 128, M / 128, 1);
    gemm_f16pair_nt<1><<<gProj, 256, GEMM_SMEM>>>(qh, ql, wqh, wql,
        nullptr, Qh, Ql, M, EE, EE, 1.0f, 0, 0, 0);
    gemm_f16pair_nt<1><<<gProj, 256, GEMM_SMEM>>>(kh, kl, wkh, wkl,
        nullptr, Kh, Kl, M, EE, EE, 1.0f, 0, 0, 0);
    gemm_f16pair_nt<0><<<gProj, 256, GEMM_SMEM>>>(vh, vl, wvh, wvl,
        V, nullptr, nullptr, M, EE, EE, 1.0f, 0, 0, 0);

    // 3b) Transpose + split V -> VT
    dim3 gT(TT / 32, EE / 32, BB);
    transpose_split_kernel<<<gT, 256>>>(V, VTh, VTl);

    // 4) Scores: S_b = (Q_b K_b^T) / 32   (M=N=2048, K=1024, batched)
    dim3 gScore(TT / 128, TT / 128, BB);
    gemm_f16pair_nt<0><<<gScore, 256, GEMM_SMEM>>>(Qh, Ql, Kh, Kl,
        S, nullptr, nullptr, TT, TT, EE, 1.0f / 32.0f, strQKV, strQKV, strS);

    // 5) Masked softmax -> split fp16 P
    softmax_split_kernel<<<BB * TT, 256>>>(S, mask, Ph, Pl);

    // 6) Output: O_b = P_b VT_b^T  (M=2048, N=1024, K=2048, batched)
    dim3 gOut(EE / 128, TT / 128, BB);
    gemm_f16pair_nt<0><<<gOut, 256, GEMM_SMEM>>>(Ph, Pl, VTh, VTl,
        out, nullptr, nullptr, TT, EE, TT, 1.0f, strS, strVT, strQKV);
}

// round 4
// speedup vs baseline: 2.4930x; 1.0522x over previous
#include <cuda_runtime.h>
#include <cuda_fp16.h>
#include <math_constants.h>
#include <cstdint>

// Problem constants
#define BB 8
#define TT 2048
#define EE 1024
#define NQKV ((size_t)BB * TT * EE)   // 16,777,216
#define NS   ((size_t)BB * TT * TT)   // 33,554,432

// ---------------------------------------------------------------------------
// Scratch (device globals; allocation forbidden in kernel_launch)
// ---------------------------------------------------------------------------
__device__ __half g_qh[NQKV], g_ql[NQKV];
__device__ __half g_kh[NQKV], g_kl[NQKV];
__device__ __half g_vh[NQKV], g_vl[NQKV];
__device__ __half g_Wqh[EE * EE], g_Wql[EE * EE];
__device__ __half g_Wkh[EE * EE], g_Wkl[EE * EE];
__device__ __half g_Wvh[EE * EE], g_Wvl[EE * EE];
__device__ __half g_Qh[NQKV], g_Ql[NQKV];
__device__ __half g_Kh[NQKV], g_Kl[NQKV];
__device__ float  g_V[NQKV];
__device__ __half g_VTh[NQKV], g_VTl[NQKV];
__device__ float  g_S[NS];
__device__ __half g_Ph[NS], g_Pl[NS];

// ---------------------------------------------------------------------------
// Helpers
// ---------------------------------------------------------------------------
__device__ __forceinline__ uint32_t smem_u32(const void* p) {
    uint32_t a;
    asm("{ .reg .u64 t; cvta.to.shared.u64 t, %1; cvt.u32.u64 %0, t; }"
        : "=r"(a) : "l"(p));
    return a;
}

__device__ __forceinline__ void cp16(uint32_t dst_smem, const void* src_gmem) {
    asm volatile("cp.async.cg.shared.global [%0], [%1], 16;"
                 :: "r"(dst_smem), "l"(__cvta_generic_to_global(src_gmem)));
}
#define CP_COMMIT() asm volatile("cp.async.commit_group;" ::: "memory")
#define CP_WAIT1()  asm volatile("cp.async.wait_group 1;"  ::: "memory")

// ldmatrix x4 (non-transposed, b16)
__device__ __forceinline__ void ldsm4(uint32_t* r, uint32_t addr) {
    asm volatile("ldmatrix.sync.aligned.m8n8.x4.shared.b16 {%0,%1,%2,%3}, [%4];"
                 : "=r"(r[0]), "=r"(r[1]), "=r"(r[2]), "=r"(r[3]) : "r"(addr));
}

// m16n8k16 fp16 -> fp32 accumulate
__device__ __forceinline__ void mma16816(float* c,
                                         uint32_t a0, uint32_t a1, uint32_t a2, uint32_t a3,
                                         uint32_t b0, uint32_t b1) {
    asm volatile(
        "mma.sync.aligned.m16n8k16.row.col.f32.f16.f16.f32 "
        "{%0,%1,%2,%3}, {%4,%5,%6,%7}, {%8,%9}, {%0,%1,%2,%3};"
        : "+f"(c[0]), "+f"(c[1]), "+f"(c[2]), "+f"(c[3])
        : "r"(a0), "r"(a1), "r"(a2), "r"(a3), "r"(b0), "r"(b1));
}

__device__ __forceinline__ void split2(float x, __half& h, __half& l) {
    h = __float2half_rn(x);
    l = __float2half_rn(x - __half2float(h));
}

// ---------------------------------------------------------------------------
// Elementwise split: fp32 -> (hi, lo) fp16 pair. n % 4 == 0.
// ---------------------------------------------------------------------------
__global__ __launch_bounds__(256)
void split_kernel(const float* __restrict__ x, __half* __restrict__ hi,
                  __half* __restrict__ lo, size_t n)
{
    size_t i = ((size_t)blockIdx.x * blockDim.x + threadIdx.x) * 4;
    if (i >= n) return;
    float4 v = *(const float4*)(x + i);
    __half h0, h1, h2, h3, l0, l1, l2, l3;
    split2(v.x, h0, l0); split2(v.y, h1, l1);
    split2(v.z, h2, l2); split2(v.w, h3, l3);
    ((__half2*)hi)[i / 2]     = __halves2half2(h0, h1);
    ((__half2*)hi)[i / 2 + 1] = __halves2half2(h2, h3);
    ((__half2*)lo)[i / 2]     = __halves2half2(l0, l1);
    ((__half2*)lo)[i / 2 + 1] = __halves2half2(l2, l3);
}

// ---------------------------------------------------------------------------
// Split-FP16 NT GEMM on tensor cores (mma.sync m16n8k16):
//   C[M,N] = alpha * (Ah+Al)[M,K] * (Bh+Bl)[N,K]^T   (3-pass, AloBlo dropped)
// CTA: 128x128x32, 256 threads = 8 warps (2 x 4), warp tile 64x32.
// SMEM: 3 stages x 4 tiles (Ah, Al, Bh, Bl), each 128 rows x 80B (64B data).
// Fragments via ldmatrix.x4; cp.async 3-deep pipeline (wait_group 1).
// OUT_MODE 0: write fp32 C.  OUT_MODE 1: write split fp16 (Ch, Cl).
// Requires M%128==0, N%128==0, K%32==0.
// ---------------------------------------------------------------------------
#define SROW 80
#define TILE_B (128 * SROW)            // 10240
#define STAGE_B (4 * TILE_B)           // 40960
#define GEMM_SMEM (3 * STAGE_B)        // 122880

template <int OUT_MODE>
__global__ __launch_bounds__(256, 1)
void gemm_f16pair_nt(const __half* __restrict__ Ah, const __half* __restrict__ Al,
                     const __half* __restrict__ Bh, const __half* __restrict__ Bl,
                     float* __restrict__ C, __half* __restrict__ Ch,
                     __half* __restrict__ Cl,
                     int M, int N, int K, float alpha,
                     size_t sA, size_t sB, size_t sC)
{
    extern __shared__ __align__(128) char smem[];
    const uint32_t sb = smem_u32(smem);

    const int tid  = threadIdx.x;
    const int wid  = tid >> 5;
    const int lane = tid & 31;
    const int wm   = wid >> 2;          // 0..1
    const int wn   = wid & 3;           // 0..3
    const int g    = lane >> 2;         // 0..7
    const int i4   = lane & 3;          // 0..3

    const size_t z = blockIdx.z;
    const __half* pAh = Ah + z * sA;
    const __half* pAl = Al + z * sA;
    const __half* pBh = Bh + z * sB;
    const __half* pBl = Bl + z * sB;

    const int aRow0 = blockIdx.y * 128;
    const int bRow0 = blockIdx.x * 128;

    // cp.async copy indices
    const int cr0 = tid >> 2;            // rows 0..63
    const int cq  = (tid & 3);           // 16B quarter 0..3

    // ldmatrix per-lane address offsets (within a tile, excluding h offset)
    // A (m16k16 frags): lanes 0-7 -> m0-7 @+0, 8-15 -> m8-15 @+0,
    //                   16-23 -> m0-7 @+16, 24-31 -> m8-15 @+16
    const int lmA = lane & 15;
    const int lqA = (lane >> 4) & 1;
    uint32_t aoff[4];
#pragma unroll
    for (int fm = 0; fm < 4; fm++)
        aoff[fm] = (uint32_t)((wm * 64 + fm * 16 + lmA) * SROW + lqA * 16);
    // B (n16k16 covering two n8 frags): lanes 0-7 -> n0-7 @+0, 8-15 -> n0-7 @+16,
    //                                   16-23 -> n8-15 @+0, 24-31 -> n8-15 @+16
    const int bn = (lane & 7) + ((lane >> 4) << 3);
    const int bq = (lane >> 3) & 1;
    uint32_t boff[2];
#pragma unroll
    for (int fp = 0; fp < 2; fp++)
        boff[fp] = (uint32_t)((wn * 32 + fp * 16 + bn) * SROW + bq * 16);

    float acc[4][4][4];
#pragma unroll
    for (int a = 0; a < 4; a++)
#pragma unroll
        for (int b = 0; b < 4; b++)
#pragma unroll
            for (int c = 0; c < 4; c++) acc[a][b][c] = 0.0f;

    const int nch = K >> 5;

    auto issue = [&](int kc) {
        const uint32_t tb = sb + (uint32_t)(kc % 3) * STAGE_B;
        const int kofs = kc << 5;
#pragma unroll
        for (int t = 0; t < 2; t++) {
            const int r = cr0 + t * 64;
            const uint32_t so = (uint32_t)(r * SROW + cq * 16);
            const size_t goA = (size_t)(aRow0 + r) * K + kofs + cq * 8;
            const size_t goB = (size_t)(bRow0 + r) * K + kofs + cq * 8;
            cp16(tb + 0 * TILE_B + so, pAh + goA);
            cp16(tb + 1 * TILE_B + so, pAl + goA);
            cp16(tb + 2 * TILE_B + so, pBh + goB);
            cp16(tb + 3 * TILE_B + so, pBl + goB);
        }
        CP_COMMIT();
    };

    issue(0);
    issue(1);

    for (int kc = 0; kc < nch; kc++) {
        CP_WAIT1();
        __syncthreads();
        if (kc + 2 < nch) issue(kc + 2);

        const uint32_t tb = sb + (uint32_t)(kc % 3) * STAGE_B;
#pragma unroll
        for (int h = 0; h < 2; h++) {
            const uint32_t ho = (uint32_t)(h * 32);
            uint32_t ah[4][4], al[4][4];
#pragma unroll
            for (int fm = 0; fm < 4; fm++) {
                ldsm4(ah[fm], tb + 0 * TILE_B + aoff[fm] + ho);
                ldsm4(al[fm], tb + 1 * TILE_B + aoff[fm] + ho);
            }
            uint32_t bh[2][4], bl[2][4];
#pragma unroll
            for (int fp = 0; fp < 2; fp++) {
                ldsm4(bh[fp], tb + 2 * TILE_B + boff[fp] + ho);
                ldsm4(bl[fp], tb + 3 * TILE_B + boff[fp] + ho);
            }
#pragma unroll
            for (int fn = 0; fn < 4; fn++) {
                const uint32_t b0h = bh[fn >> 1][(fn & 1) * 2];
                const uint32_t b1h = bh[fn >> 1][(fn & 1) * 2 + 1];
                const uint32_t b0l = bl[fn >> 1][(fn & 1) * 2];
                const uint32_t b1l = bl[fn >> 1][(fn & 1) * 2 + 1];
#pragma unroll
                for (int fm = 0; fm < 4; fm++) {
                    mma16816(acc[fm][fn], ah[fm][0], ah[fm][1], ah[fm][2], ah[fm][3], b0h, b1h);
                    mma16816(acc[fm][fn], ah[fm][0], ah[fm][1], ah[fm][2], ah[fm][3], b0l, b1l);
                    mma16816(acc[fm][fn], al[fm][0], al[fm][1], al[fm][2], al[fm][3], b0h, b1h);
                }
            }
        }
        __syncthreads();
    }

    // Epilogue
    const int rowB = aRow0 + wm * 64 + g;
    const int colB = bRow0 + wn * 32 + i4 * 2;
#pragma unroll
    for (int fm = 0; fm < 4; fm++) {
#pragma unroll
        for (int fn = 0; fn < 4; fn++) {
            const int row = rowB + fm * 16;
            const int col = colB + fn * 8;
            float c0 = alpha * acc[fm][fn][0];
            float c1 = alpha * acc[fm][fn][1];
            float c2 = alpha * acc[fm][fn][2];
            float c3 = alpha * acc[fm][fn][3];
            if (OUT_MODE == 0) {
                float* pc = C + z * sC;
                *(float2*)(pc + (size_t)row * N + col)       = make_float2(c0, c1);
                *(float2*)(pc + (size_t)(row + 8) * N + col) = make_float2(c2, c3);
            } else {
                __half* ph = Ch + z * sC;
                __half* pl = Cl + z * sC;
                __half h0, h1, h2, h3, l0, l1, l2, l3;
                split2(c0, h0, l0); split2(c1, h1, l1);
                split2(c2, h2, l2); split2(c3, h3, l3);
                *(__half2*)(ph + (size_t)row * N + col)       = __halves2half2(h0, h1);
                *(__half2*)(pl + (size_t)row * N + col)       = __halves2half2(l0, l1);
                *(__half2*)(ph + (size_t)(row + 8) * N + col) = __halves2half2(h2, h3);
                *(__half2*)(pl + (size_t)(row + 8) * N + col) = __halves2half2(l2, l3);
            }
        }
    }
}

// ---------------------------------------------------------------------------
// Transpose + split: V[b][s][o] fp32 -> VThi/VTlo[b][o][s] fp16
// ---------------------------------------------------------------------------
__global__ __launch_bounds__(256)
void transpose_split_kernel(const float* __restrict__ V,
                            __half* __restrict__ Th, __half* __restrict__ Tl)
{
    __shared__ float t[32][33];
    const int b  = blockIdx.z;
    const int s0 = blockIdx.x << 5;
    const int o0 = blockIdx.y << 5;
    const float* Vb = V + (size_t)b * TT * EE;
    __half* Thb = Th + (size_t)b * EE * TT;
    __half* Tlb = Tl + (size_t)b * EE * TT;
    const int tx = threadIdx.x & 31;
    const int ty = threadIdx.x >> 5;
#pragma unroll
    for (int i = 0; i < 4; i++)
        t[ty + 8 * i][tx] = Vb[(size_t)(s0 + ty + 8 * i) * EE + o0 + tx];
    __syncthreads();
#pragma unroll
    for (int i = 0; i < 4; i++) {
        float x = t[tx][ty + 8 * i];
        __half h, l;
        split2(x, h, l);
        const size_t off = (size_t)(o0 + ty + 8 * i) * TT + s0 + tx;
        Thb[off] = h;
        Tlb[off] = l;
    }
}

// ---------------------------------------------------------------------------
// Masked row softmax: S[B*T, T] fp32 -> split fp16 (Ph, Pl). mask 0 -> -inf.
// ---------------------------------------------------------------------------
__global__ __launch_bounds__(256)
void softmax_split_kernel(const float* __restrict__ S, const int* __restrict__ mask,
                          __half* __restrict__ Ph, __half* __restrict__ Pl)
{
    const int row = blockIdx.x;
    const int t   = row & (TT - 1);
    const float* Srow = S + (size_t)row * TT;
    const int* mrow = mask + (size_t)t * TT;
    const int tid = threadIdx.x;

    float v[8];
    float m = -CUDART_INF_F;
#pragma unroll
    for (int i = 0; i < 8; i++) {
        int s = tid + i * 256;
        float x = (mrow[s] != 0) ? Srow[s] : -CUDART_INF_F;
        v[i] = x;
        m = fmaxf(m, x);
    }

    __shared__ float red[256];
    red[tid] = m;
    __syncthreads();
    for (int off = 128; off > 0; off >>= 1) {
        if (tid < off) red[tid] = fmaxf(red[tid], red[tid + off]);
        __syncthreads();
    }
    m = red[0];
    __syncthreads();

    float sum = 0.0f;
#pragma unroll
    for (int i = 0; i < 8; i++) {
        float e = __expf(v[i] - m);
        v[i] = e;
        sum += e;
    }
    red[tid] = sum;
    __syncthreads();
    for (int off = 128; off > 0; off >>= 1) {
        if (tid < off) red[tid] += red[tid + off];
        __syncthreads();
    }
    const float inv = 1.0f / red[0];

    __half* Phr = Ph + (size_t)row * TT;
    __half* Plr = Pl + (size_t)row * TT;
#pragma unroll
    for (int i = 0; i < 8; i++) {
        float p = v[i] * inv;
        __half h, l;
        split2(p, h, l);
        Phr[tid + i * 256] = h;
        Plr[tid + i * 256] = l;
    }
}

// ---------------------------------------------------------------------------
// kernel_launch
// ---------------------------------------------------------------------------
extern "C" void kernel_launch(void* const* d_in, const int* in_sizes, int n_in,
                              void* d_out, int out_size)
{
    const float* q    = (const float*)d_in[0];
    const float* k    = (const float*)d_in[1];
    const float* v    = (const float*)d_in[2];
    const int*   mask = (const int*)  d_in[3];
    const float* Wq   = (const float*)d_in[4];
    const float* Wk   = (const float*)d_in[5];
    const float* Wv   = (const float*)d_in[6];
    float* out = (float*)d_out;

    __half *qh, *ql, *kh, *kl, *vh, *vl;
    __half *wqh, *wql, *wkh, *wkl, *wvh, *wvl;
    __half *Qh, *Ql, *Kh, *Kl, *VTh, *VTl, *Ph, *Pl;
    float *V, *S;
    cudaGetSymbolAddress((void**)&qh,  g_qh);  cudaGetSymbolAddress((void**)&ql,  g_ql);
    cudaGetSymbolAddress((void**)&kh,  g_kh);  cudaGetSymbolAddress((void**)&kl,  g_kl);
    cudaGetSymbolAddress((void**)&vh,  g_vh);  cudaGetSymbolAddress((void**)&vl,  g_vl);
    cudaGetSymbolAddress((void**)&wqh, g_Wqh); cudaGetSymbolAddress((void**)&wql, g_Wql);
    cudaGetSymbolAddress((void**)&wkh, g_Wkh); cudaGetSymbolAddress((void**)&wkl, g_Wkl);
    cudaGetSymbolAddress((void**)&wvh, g_Wvh); cudaGetSymbolAddress((void**)&wvl, g_Wvl);
    cudaGetSymbolAddress((void**)&Qh,  g_Qh);  cudaGetSymbolAddress((void**)&Ql,  g_Ql);
    cudaGetSymbolAddress((void**)&Kh,  g_Kh);  cudaGetSymbolAddress((void**)&Kl,  g_Kl);
    cudaGetSymbolAddress((void**)&VTh, g_VTh); cudaGetSymbolAddress((void**)&VTl, g_VTl);
    cudaGetSymbolAddress((void**)&Ph,  g_Ph);  cudaGetSymbolAddress((void**)&Pl,  g_Pl);
    cudaGetSymbolAddress((void**)&V,   g_V);
    cudaGetSymbolAddress((void**)&S,   g_S);

    cudaFuncSetAttribute(gemm_f16pair_nt<0>,
                         cudaFuncAttributeMaxDynamicSharedMemorySize, GEMM_SMEM);
    cudaFuncSetAttribute(gemm_f16pair_nt<1>,
                         cudaFuncAttributeMaxDynamicSharedMemorySize, GEMM_SMEM);

    const int M = BB * TT;                   // 16384
    const size_t strQKV = (size_t)TT * EE;
    const size_t strS   = (size_t)TT * TT;
    const size_t strVT  = (size_t)EE * TT;

    // 0) Split fp32 inputs into fp16 (hi, lo) pairs
    {
        const int nb_big = (int)(NQKV / (256 * 4));
        const int nb_w   = (EE * EE) / (256 * 4);
        split_kernel<<<nb_big, 256>>>(q,  qh,  ql,  NQKV);
        split_kernel<<<nb_big, 256>>>(k,  kh,  kl,  NQKV);
        split_kernel<<<nb_big, 256>>>(v,  vh,  vl,  NQKV);
        split_kernel<<<nb_w,   256>>>(Wq, wqh, wql, (size_t)EE * EE);
        split_kernel<<<nb_w,   256>>>(Wk, wkh, wkl, (size_t)EE * EE);
        split_kernel<<<nb_w,   256>>>(Wv, wvh, wvl, (size_t)EE * EE);
    }

    // 1-3) Projections (M=16384, N=1024, K=1024)
    dim3 gProj(EE / 128, M / 128, 1);
    gemm_f16pair_nt<1><<<gProj, 256, GEMM_SMEM>>>(qh, ql, wqh, wql,
        nullptr, Qh, Ql, M, EE, EE, 1.0f, 0, 0, 0);
    gemm_f16pair_nt<1><<<gProj, 256, GEMM_SMEM>>>(kh, kl, wkh, wkl,
        nullptr, Kh, Kl, M, EE, EE, 1.0f, 0, 0, 0);
    gemm_f16pair_nt<0><<<gProj, 256, GEMM_SMEM>>>(vh, vl, wvh, wvl,
        V, nullptr, nullptr, M, EE, EE, 1.0f, 0, 0, 0);

    // 3b) Transpose + split V -> VT
    dim3 gT(TT / 32, EE / 32, BB);
    transpose_split_kernel<<<gT, 256>>>(V, VTh, VTl);

    // 4) Scores: S_b = (Q_b K_b^T) / 32   (M=N=2048, K=1024, batched)
    dim3 gScore(TT / 128, TT / 128, BB);
    gemm_f16pair_nt<0><<<gScore, 256, GEMM_SMEM>>>(Qh, Ql, Kh, Kl,
        S, nullptr, nullptr, TT, TT, EE, 1.0f / 32.0f, strQKV, strQKV, strS);

    // 5) Masked softmax -> split fp16 P
    softmax_split_kernel<<<BB * TT, 256>>>(S, mask, Ph, Pl);

    // 6) Output: O_b = P_b VT_b^T  (M=2048, N=1024, K=2048, batched)
    dim3 gOut(EE / 128, TT / 128, BB);
    gemm_f16pair_nt<0><<<gOut, 256, GEMM_SMEM>>>(Ph, Pl, VTh, VTl,
        out, nullptr, nullptr, TT, EE, TT, 1.0f, strS, strVT, strQKV);
}